// round 17
// baseline (speedup 1.0000x reference)
#include <cuda_runtime.h>
#include <cuda_fp16.h>
#include <cstdint>

#define BATCH 2
#define SEQ   2048
#define HEADS 16
#define DH    64
#define DMODEL 1024
#define MTOT  (BATCH*SEQ)   // 4096
#define STRG  72            // GEMM smem stride (halves), BK=64 + pad 8
#define STRK  72            // attn K/Q smem stride (halves)
#define STRV  136           // attn V smem stride (halves): 128 + pad 8
#define QSCALE 0.18033688011112042f   // 0.125 * log2(e), folded into Q

// ---------------- scratch (allocation-free rule: __device__ globals) --------
__device__ __align__(16) __half g_xh[MTOT*DMODEL];        // fp16 x
__device__ __align__(16) __half g_wth[3*DMODEL*DMODEL];   // Wq/Wk/Wv^T [n][k]
__device__ __align__(16) __half g_woth[DMODEL*DMODEL];    // Wo^T [n][k]
__device__ __align__(16) __half g_q[BATCH*HEADS*SEQ*DH];  // [b,h,t,d] (pre-scaled)
__device__ __align__(16) __half g_k[BATCH*HEADS*SEQ*DH];  // [b,h,t,d]
__device__ __align__(16) __half g_vt[BATCH*HEADS*SEQ*DH]; // [b,h,d,t]
__device__ __align__(16) __half g_ctx[BATCH*SEQ*DMODEL];  // [b,t,h*64+d]

// ---------------- helpers ----------------------------------------------------
__device__ __forceinline__ uint32_t smem_u32(const void* p) {
    uint32_t a;
    asm("{ .reg .u64 t; cvta.to.shared.u64 t, %1; cvt.u32.u64 %0, t; }"
        : "=r"(a) : "l"(p));
    return a;
}
__device__ __forceinline__ uint32_t f22u(float lo, float hi) {
    __half2 h = __floats2half2_rn(lo, hi);
    return *reinterpret_cast<uint32_t*>(&h);
}
__device__ __forceinline__ uint32_t exp2h2(uint32_t x) {
    uint32_t r;
    asm("ex2.approx.f16x2 %0, %1;" : "=r"(r) : "r"(x));
    return r;
}
__device__ __forceinline__ void cp_async16(uint32_t s, const void* g) {
    asm volatile("cp.async.cg.shared.global [%0], [%1], 16;" :: "r"(s), "l"(g));
}
__device__ __forceinline__ void cp_commit() {
    asm volatile("cp.async.commit_group;" ::: "memory");
}
template<int N> __device__ __forceinline__ void cp_wait() {
    asm volatile("cp.async.wait_group %0;" :: "n"(N) : "memory");
}
// fp16 HMMA, fp32 C
__device__ __forceinline__ void mma_f16(float c[4], const uint32_t a[4], const uint32_t b[2]) {
    asm volatile(
        "mma.sync.aligned.m16n8k16.row.col.f32.f16.f16.f32 "
        "{%0,%1,%2,%3}, {%4,%5,%6,%7}, {%8,%9}, {%0,%1,%2,%3};"
        : "+f"(c[0]), "+f"(c[1]), "+f"(c[2]), "+f"(c[3])
        : "r"(a[0]), "r"(a[1]), "r"(a[2]), "r"(a[3]), "r"(b[0]), "r"(b[1]));
}
// fp16 HMMA, fp16 C (double-rate)
__device__ __forceinline__ void mma_f16h(uint32_t c[2], const uint32_t a[4], const uint32_t b[2]) {
    asm volatile(
        "mma.sync.aligned.m16n8k16.row.col.f16.f16.f16.f16 "
        "{%0,%1}, {%2,%3,%4,%5}, {%6,%7}, {%0,%1};"
        : "+r"(c[0]), "+r"(c[1])
        : "r"(a[0]), "r"(a[1]), "r"(a[2]), "r"(a[3]), "r"(b[0]), "r"(b[1]));
}
__device__ __forceinline__ void ldsm4(uint32_t r[4], uint32_t addr) {
    asm volatile("ldmatrix.sync.aligned.m8n8.x4.shared.b16 {%0,%1,%2,%3}, [%4];"
        : "=r"(r[0]), "=r"(r[1]), "=r"(r[2]), "=r"(r[3]) : "r"(addr));
}

// =====================================================================
// Pre-pass A: fp16-round x
// =====================================================================
__global__ void __launch_bounds__(256) convert_x_kernel(const float* __restrict__ x) {
    int idx = blockIdx.x * 256 + threadIdx.x;          // 8 floats each
    float4 v0 = *reinterpret_cast<const float4*>(x + idx * 8);
    float4 v1 = *reinterpret_cast<const float4*>(x + idx * 8 + 4);
    uint4 o;
    o.x = f22u(v0.x, v0.y); o.y = f22u(v0.z, v0.w);
    o.z = f22u(v1.x, v1.y); o.w = f22u(v1.z, v1.w);
    *reinterpret_cast<uint4*>(g_xh + idx * 8) = o;
}

// =====================================================================
// Pre-pass B: transpose + fp16-round the 4 weight matrices -> [n][k]
// =====================================================================
__global__ void __launch_bounds__(256) transpose_w_kernel(
    const float* __restrict__ Wq, const float* __restrict__ Wk,
    const float* __restrict__ Wv, const float* __restrict__ Wo)
{
    __shared__ float tile[32][33];
    int mat = blockIdx.z;
    const float* src = (mat == 0) ? Wq : (mat == 1) ? Wk : (mat == 2) ? Wv : Wo;
    __half* dst = (mat < 3) ? (g_wth + (size_t)mat * DMODEL * DMODEL) : g_woth;
    int bx = blockIdx.x * 32, by = blockIdx.y * 32;
    int tx = threadIdx.x, ty = threadIdx.y;    // 32 x 8
    #pragma unroll
    for (int i = 0; i < 32; i += 8)
        tile[ty + i][tx] = src[(by + ty + i) * DMODEL + bx + tx];
    __syncthreads();
    #pragma unroll
    for (int i = 0; i < 32; i += 8)
        dst[(size_t)(bx + ty + i) * DMODEL + by + tx] = __float2half(tile[tx][ty + i]);
}

// =====================================================================
// fp16 GEMM mainloop, ldmatrix frags, 2-stage single-sync pipeline, BK=64.
// =====================================================================
__device__ __forceinline__ void f16_gemm_tile(
    const __half* __restrict__ A, const __half* __restrict__ Bt,
    int mBase, int nBase, float acc[2][8][4])
{
    extern __shared__ __half smh[];
    __half* AsBuf[2] = { smh,              smh + 2 * 128 * STRG };
    __half* BsBuf[2] = { smh + 128 * STRG, smh + 3 * 128 * STRG };

    const int tid  = threadIdx.x;
    const int wid  = tid >> 5;
    const int lane = tid & 31;
    const int wm = (wid & 3) * 32;
    const int wn = (wid >> 2) * 64;
    const int aRow = lane & 15;
    const int aK   = (lane >> 4) << 3;
    const int bRow = (lane & 7) | ((lane >> 4) << 3);
    const int bK   = ((lane >> 3) & 1) << 3;

    #pragma unroll
    for (int mt = 0; mt < 2; ++mt)
        #pragma unroll
        for (int nt = 0; nt < 8; ++nt)
            #pragma unroll
            for (int i = 0; i < 4; ++i) acc[mt][nt][i] = 0.0f;

    #define STAGE(buf, kt) do {                                                   \
        const __half* Ag_ = A  + (size_t)mBase * DMODEL + (kt) * 64;               \
        const __half* Bg_ = Bt + (size_t)nBase * DMODEL + (kt) * 64;               \
        _Pragma("unroll")                                                          \
        for (int i_ = 0; i_ < 4; ++i_) {                                           \
            int idx_ = tid + 256 * i_;                                             \
            int row_ = idx_ >> 3, c_ = idx_ & 7;                                   \
            cp_async16(smem_u32(AsBuf[buf] + row_ * STRG + c_ * 8),                \
                       Ag_ + (size_t)row_ * DMODEL + c_ * 8);                      \
            cp_async16(smem_u32(BsBuf[buf] + row_ * STRG + c_ * 8),                \
                       Bg_ + (size_t)row_ * DMODEL + c_ * 8);                      \
        }                                                                          \
        cp_commit();                                                               \
    } while (0)

    STAGE(0, 0);

    for (int kt = 0; kt < 16; ++kt) {
        const int buf = kt & 1;
        cp_wait<0>();
        __syncthreads();
        if (kt + 1 < 16) STAGE(buf ^ 1, kt + 1);

        const uint32_t aBase = smem_u32(AsBuf[buf]) + ((wm + aRow) * STRG + aK) * 2;
        const uint32_t bBase = smem_u32(BsBuf[buf]) + ((wn + bRow) * STRG + bK) * 2;
        #pragma unroll
        for (int ks = 0; ks < 4; ++ks) {
            uint32_t a[2][4];
            ldsm4(a[0], aBase + ks * 32);
            ldsm4(a[1], aBase + (16 * STRG) * 2 + ks * 32);
            #pragma unroll
            for (int ntp = 0; ntp < 4; ++ntp) {
                uint32_t b[4];
                ldsm4(b, bBase + (ntp * 16 * STRG) * 2 + ks * 32);
                mma_f16(acc[0][2 * ntp],     a[0], b);
                mma_f16(acc[0][2 * ntp + 1], a[0], b + 2);
                mma_f16(acc[1][2 * ntp],     a[1], b);
                mma_f16(acc[1][2 * ntp + 1], a[1], b + 2);
            }
        }
    }
    __syncthreads();
    #undef STAGE
}

#define GEMM_SMEM (4 * 128 * STRG * (int)sizeof(__half))   // 73728 B

// =====================================================================
// QKV projection. Q (pre-scaled by QSCALE), K -> [b,h,t,d]. V -> g_vt [b,h,d,t].
// =====================================================================
__global__ void __launch_bounds__(256, 2) qkv_mma_kernel()
{
    const int mBase = blockIdx.y * 128;
    const int nGlob = blockIdx.x * 128;
    const int which = nGlob >> 10;
    const int nBase = nGlob & (DMODEL - 1);
    const __half* B = g_wth + (size_t)which * DMODEL * DMODEL;

    float acc[2][8][4];
    f16_gemm_tile(g_xh, B, mBase, nBase, acc);

    const int tid  = threadIdx.x;
    const int wid  = tid >> 5;
    const int lane = tid & 31;
    const int wm = (wid & 3) * 32;
    const int wn = (wid >> 2) * 64;
    const int g = lane >> 2;
    const int t = lane & 3;
    const int h = ((nBase + wn) >> 6) & 15;

    if (which == 2) {
        // V: write transposed [b,h,d,t]
        #pragma unroll
        for (int mt = 0; mt < 2; ++mt) {
            #pragma unroll
            for (int half = 0; half < 2; ++half) {
                const int m  = mBase + wm + mt * 16 + g + half * 8;
                const int bb = m >> 11;
                const int tt = m & (SEQ - 1);
                __half* base = g_vt + ((size_t)(bb * HEADS + h) * DH) * SEQ + tt;
                #pragma unroll
                for (int nt = 0; nt < 8; ++nt) {
                    const int dl = nt * 8 + 2 * t;
                    float c0 = half ? acc[mt][nt][2] : acc[mt][nt][0];
                    float c1 = half ? acc[mt][nt][3] : acc[mt][nt][1];
                    base[(size_t)dl * SEQ]       = __float2half(c0);
                    base[(size_t)(dl + 1) * SEQ] = __float2half(c1);
                }
            }
        }
    } else {
        __half* dstbase = (which == 0) ? g_q : g_k;
        const float sc = (which == 0) ? QSCALE : 1.0f;
        #pragma unroll
        for (int mt = 0; mt < 2; ++mt) {
            #pragma unroll
            for (int half = 0; half < 2; ++half) {
                const int m  = mBase + wm + mt * 16 + g + half * 8;
                const int bb = m >> 11;
                const int tt = m & (SEQ - 1);
                __half* dp = dstbase + ((size_t)(bb * HEADS + h) * SEQ + tt) * DH;
                #pragma unroll
                for (int nt = 0; nt < 8; ++nt) {
                    const int d = nt * 8 + 2 * t;
                    uint32_t v = half ? f22u(acc[mt][nt][2] * sc, acc[mt][nt][3] * sc)
                                      : f22u(acc[mt][nt][0] * sc, acc[mt][nt][1] * sc);
                    *reinterpret_cast<uint32_t*>(dp + d) = v;
                }
            }
        }
    }
}

// =====================================================================
// Output projection: out = ctx @ Wo + bo (fp32 out)
// =====================================================================
__global__ void __launch_bounds__(256, 2) outproj_mma_kernel(
    const float* __restrict__ bo, float* __restrict__ out)
{
    const int mBase = blockIdx.y * 128;
    const int nBase = blockIdx.x * 128;

    float acc[2][8][4];
    f16_gemm_tile(g_ctx, g_woth, mBase, nBase, acc);

    const int tid  = threadIdx.x;
    const int wid  = tid >> 5;
    const int lane = tid & 31;
    const int wm = (wid & 3) * 32;
    const int wn = (wid >> 2) * 64;
    const int g = lane >> 2;
    const int t = lane & 3;

    float2 bias[8];
    #pragma unroll
    for (int nt = 0; nt < 8; ++nt)
        bias[nt] = *reinterpret_cast<const float2*>(bo + nBase + wn + nt * 8 + 2 * t);

    #pragma unroll
    for (int mt = 0; mt < 2; ++mt) {
        #pragma unroll
        for (int half = 0; half < 2; ++half) {
            const int m = mBase + wm + mt * 16 + g + half * 8;
            float* dp = out + (size_t)m * DMODEL + nBase + wn;
            #pragma unroll
            for (int nt = 0; nt < 8; ++nt) {
                const int d = nt * 8 + 2 * t;
                float2 v = half ? make_float2(acc[mt][nt][2], acc[mt][nt][3])
                                : make_float2(acc[mt][nt][0], acc[mt][nt][1]);
                v.x += bias[nt].x;
                v.y += bias[nt].y;
                *reinterpret_cast<float2*>(dp + d) = v;
            }
        }
    }
}

// =====================================================================
// Causal flash attention: 128-key staged tiles (2-stage, single-sync),
// computed as two 64-key sub-blocks (register footprint unchanged).
// S via double-rate fp16-C MMA, ex2 on C-frags, PV + row-sum fp32-C.
// =====================================================================
#define ATTN_SMEM ((128*STRK + 2*(128*STRK + 64*STRV)) * (int)sizeof(__half))  // 90112 B

__global__ void __launch_bounds__(256, 2) attn_mma_kernel()
{
    extern __shared__ __half smh[];
    __half* Qs = smh;
    __half* KsB[2] = { smh + 128*STRK,
                       smh + 128*STRK + (128*STRK + 64*STRV) };
    __half* VsB[2] = { smh + 128*STRK + 128*STRK,
                       smh + 128*STRK + (128*STRK + 64*STRV) + 128*STRK };

    const int tid  = threadIdx.x;
    const int wid  = tid >> 5;
    const int lane = tid & 31;
    const int g = lane >> 2;
    const int t = lane & 3;
    const int qpair = blockIdx.x;        // 0..7
    const int bh    = blockIdx.y;        // 0..31
    const int wm    = wid * 16;
    const int aRow = lane & 15;
    const int aK   = (lane >> 4) << 3;
    const int bRow = (lane & 7) | ((lane >> 4) << 3);
    const int bK   = ((lane >> 3) & 1) << 3;

    const __half* Kg  = g_k  + (size_t)bh * SEQ * DH;
    const __half* Vtg = g_vt + (size_t)bh * DH * SEQ;
    const int bb = bh >> 4;
    const int h  = bh & 15;
    const uint32_t onesb[2] = { 0x3C003C00u, 0x3C003C00u };
    const __half2 thirty = __floats2half2_rn(30.0f, 30.0f);

    // stage one 128-key K tile + matching [64 d][128 t] V tile
    #define STAGEKV(buf, j) do {                                                    \
        const __half* kp_ = Kg + (size_t)(j) * 128 * DH;                             \
        const __half* vp_ = Vtg + (size_t)(j) * 128;                                 \
        _Pragma("unroll")                                                            \
        for (int i_ = 0; i_ < 4; ++i_) {                                             \
            int idx_ = tid + 256 * i_;                                               \
            int krow_ = idx_ >> 3, kc_ = idx_ & 7;                                   \
            cp_async16(smem_u32(KsB[buf] + krow_ * STRK + kc_ * 8),                  \
                       kp_ + (size_t)krow_ * DH + kc_ * 8);                          \
            int vrow_ = idx_ >> 4, vc_ = idx_ & 15;                                  \
            cp_async16(smem_u32(VsB[buf] + vrow_ * STRV + vc_ * 8),                  \
                       vp_ + (size_t)vrow_ * SEQ + vc_ * 8);                         \
        }                                                                            \
        cp_commit();                                                                 \
    } while (0)

    #pragma unroll 1
    for (int pass = 0; pass < 2; ++pass) {
        const int qtile = pass ? qpair : (15 - qpair);   // heavy tile first
        if (pass) __syncthreads();

        const int njt = qtile + 1;                       // 128-key tiles
        const __half* Qg = g_q + ((size_t)bh * SEQ + qtile * 128) * DH;
        #pragma unroll
        for (int i = 0; i < 4; ++i) {
            int idx = tid + 256 * i;
            int row = idx >> 3, c = idx & 7;
            cp_async16(smem_u32(Qs + row * STRK + c * 8), Qg + (size_t)row * DH + c * 8);
        }
        STAGEKV(0, 0);

        float O[8][4];
        #pragma unroll
        for (int dt = 0; dt < 8; ++dt)
            #pragma unroll
            for (int i = 0; i < 4; ++i) O[dt][i] = 0.0f;
        float Ol[4] = { 0.0f, 0.0f, 0.0f, 0.0f };   // row sums via ones-MMA

        const int q0row = qtile * 128 + wm + g;
        const int q1row = q0row + 8;
        const __half2 row0h = __floats2half2_rn((float)q0row, (float)q0row);
        const __half2 row1h = __floats2half2_rn((float)q1row, (float)q1row);
        const uint32_t qBase = smem_u32(Qs) + ((wm + aRow) * STRK + aK) * 2;

        #pragma unroll 1
        for (int j = 0; j < njt; ++j) {
            const int buf = j & 1;
            cp_wait<0>();
            __syncthreads();
            if (j + 1 < njt) STAGEKV(buf ^ 1, j + 1);

            #pragma unroll
            for (int sub = 0; sub < 2; ++sub) {
                const int jj = 2 * j + sub;              // 64-key sub-block index
                if (64 * jj > qtile * 128 + wm + 15) break;

                const uint32_t kBase = smem_u32(KsB[buf]) +
                    ((sub * 64 + bRow) * STRK + bK) * 2;
                const uint32_t vBase = smem_u32(VsB[buf]) +
                    (bRow * STRV + sub * 64 + bK) * 2;

                // ---- S = Qs K^T, fp16 accumulators (double-rate HMMA) ----
                uint32_t sc[8][2];
                #pragma unroll
                for (int nt = 0; nt < 8; ++nt) { sc[nt][0] = 0u; sc[nt][1] = 0u; }

                #pragma unroll
                for (int ks = 0; ks < 4; ++ks) {
                    uint32_t a[4];
                    ldsm4(a, qBase + ks * 32);
                    #pragma unroll
                    for (int ntp = 0; ntp < 4; ++ntp) {
                        uint32_t b[4];
                        ldsm4(b, kBase + (ntp * 16 * STRK) * 2 + ks * 32);
                        mma_f16h(sc[2 * ntp],     a, b);
                        mma_f16h(sc[2 * ntp + 1], a, b + 2);
                    }
                }

                // ---- causal mask (diagonal sub-blocks): s -= 30 where col > row ----
                if (jj >= 2 * qtile) {
                    #pragma unroll
                    for (int nt = 0; nt < 8; ++nt) {
                        const int col = 64 * jj + nt * 8 + 2 * t;
                        __half2 colh = __floats2half2_rn((float)col, (float)(col + 1));
                        __half2 s0 = *reinterpret_cast<__half2*>(&sc[nt][0]);
                        __half2 s1 = *reinterpret_cast<__half2*>(&sc[nt][1]);
                        s0 = __hsub2(s0, __hmul2(__hgt2(colh, row0h), thirty));
                        s1 = __hsub2(s1, __hmul2(__hgt2(colh, row1h), thirty));
                        sc[nt][0] = *reinterpret_cast<uint32_t*>(&s0);
                        sc[nt][1] = *reinterpret_cast<uint32_t*>(&s1);
                    }
                }

                // ---- p = 2^s on C-frags; O += P V; l += P @ ones ----
                #pragma unroll
                for (int ks = 0; ks < 4; ++ks) {
                    uint32_t a[4];
                    a[0] = exp2h2(sc[2*ks][0]);
                    a[1] = exp2h2(sc[2*ks][1]);
                    a[2] = exp2h2(sc[2*ks+1][0]);
                    a[3] = exp2h2(sc[2*ks+1][1]);
                    mma_f16(Ol, a, onesb);
                    #pragma unroll
                    for (int dtp = 0; dtp < 4; ++dtp) {
                        uint32_t b[4];
                        ldsm4(b, vBase + (dtp * 16 * STRV) * 2 + ks * 32);
                        mma_f16(O[2 * dtp],     a, b);
                        mma_f16(O[2 * dtp + 1], a, b + 2);
                    }
                }
            }
        }

        // ---- epilogue: O / l -> g_ctx (fp16) ----
        const float inv0 = 1.0f / Ol[0];
        const float inv1 = 1.0f / Ol[2];
        __half* c0p = g_ctx + ((size_t)bb * SEQ + q0row) * DMODEL + h * 64;
        __half* c1p = g_ctx + ((size_t)bb * SEQ + q1row) * DMODEL + h * 64;
        #pragma unroll
        for (int dt = 0; dt < 8; ++dt) {
            *reinterpret_cast<uint32_t*>(c0p + dt * 8 + 2 * t) =
                f22u(O[dt][0] * inv0, O[dt][1] * inv0);
            *reinterpret_cast<uint32_t*>(c1p + dt * 8 + 2 * t) =
                f22u(O[dt][2] * inv1, O[dt][3] * inv1);
        }
    }
    #undef STAGEKV
}

// =====================================================================
extern "C" void kernel_launch(void* const* d_in, const int* in_sizes, int n_in,
                              void* d_out, int out_size)
{
    (void)in_sizes; (void)n_in; (void)out_size;
    const float* x  = (const float*)d_in[0];
    const float* Wq = (const float*)d_in[1];
    const float* Wk = (const float*)d_in[2];
    const float* Wv = (const float*)d_in[3];
    const float* Wo = (const float*)d_in[4];
    const float* bo = (const float*)d_in[5];
    float* out = (float*)d_out;

    cudaFuncSetAttribute((const void*)qkv_mma_kernel,
                         cudaFuncAttributeMaxDynamicSharedMemorySize, GEMM_SMEM);
    cudaFuncSetAttribute((const void*)outproj_mma_kernel,
                         cudaFuncAttributeMaxDynamicSharedMemorySize, GEMM_SMEM);
    cudaFuncSetAttribute((const void*)attn_mma_kernel,
                         cudaFuncAttributeMaxDynamicSharedMemorySize, ATTN_SMEM);

    convert_x_kernel<<<MTOT * DMODEL / 2048, 256>>>(x);
    transpose_w_kernel<<<dim3(32, 32, 4), dim3(32, 8)>>>(Wq, Wk, Wv, Wo);
    qkv_mma_kernel<<<dim3(24, 32), 256, GEMM_SMEM>>>();
    attn_mma_kernel<<<dim3(8, 32), 256, ATTN_SMEM>>>();
    outproj_mma_kernel<<<dim3(8, 32), 256, GEMM_SMEM>>>(bo, out);
}